// round 4
// baseline (speedup 1.0000x reference)
#include <cuda_runtime.h>

// ---------------------------------------------------------------------------
// MoE LoRA delta: delta = sum_e gate[t,e] * (x A_e^T) B_e^T * scale
//   x:  (T=8192, D=4096) f32       router_w: (E=4, D) f32
//   A:  (E, R=16, D) f32  -> A_flat (64, D) contiguous
//   B:  (E, O=4096, R) f32 -> transposed to Bf (64, O)
// Pipeline:
//   K1 router  : logits + top-2 softmax -> gates (scaled by 4.0)
//   K2 midGEMM : midp[s] = x @ A_flat^T  (K split 8 ways, 128x64 tile, 8x4)
//   K3 transB  : Bf[er][o] = B[e][o][r]
//   K4 combine : gmid[t][er] = gates[t][e] * sum_s midp[s][t][er]
//   K5 outGEMM : out = gmid @ Bf          (128x128 tile, 8x8, K-chunk 32)
// ---------------------------------------------------------------------------

#define D_DIM   4096
#define E_EXP   4
#define R_RANK  16
#define ER      64
#define O_DIM   4096
#define MAXT    8192
#define LSCALE  4.0f
#define KSPLIT  8

// static scratch (allowed; no runtime allocation)
__device__ float g_midp[KSPLIT][MAXT][ER];   // 16 MB
__device__ float g_gmid[MAXT][ER];           // 2 MB
__device__ float g_gates[MAXT][E_EXP];       // 128 KB
__device__ float g_Bf[ER][O_DIM];            // 1 MB

// ---------------------------------------------------------------------------
// K1: one warp per token. logits (4 dots of length 4096), top-2 softmax.
// ---------------------------------------------------------------------------
__global__ __launch_bounds__(256)
void router_kernel(const float* __restrict__ x, const float* __restrict__ rw, int T)
{
    int warp = (blockIdx.x * blockDim.x + threadIdx.x) >> 5;
    int lane = threadIdx.x & 31;
    if (warp >= T) return;

    const float4* xr = reinterpret_cast<const float4*>(x + (size_t)warp * D_DIM);
    const float4* w4 = reinterpret_cast<const float4*>(rw);

    float a0 = 0.f, a1 = 0.f, a2 = 0.f, a3 = 0.f;
    const int K4 = D_DIM / 4;  // 1024
    for (int k = lane; k < K4; k += 32) {
        float4 xv = xr[k];
        float4 w0 = w4[k];
        float4 w1 = w4[K4 + k];
        float4 w2 = w4[2 * K4 + k];
        float4 w3 = w4[3 * K4 + k];
        a0 += xv.x * w0.x + xv.y * w0.y + xv.z * w0.z + xv.w * w0.w;
        a1 += xv.x * w1.x + xv.y * w1.y + xv.z * w1.z + xv.w * w1.w;
        a2 += xv.x * w2.x + xv.y * w2.y + xv.z * w2.z + xv.w * w2.w;
        a3 += xv.x * w3.x + xv.y * w3.y + xv.z * w3.z + xv.w * w3.w;
    }
    #pragma unroll
    for (int off = 16; off; off >>= 1) {
        a0 += __shfl_xor_sync(0xffffffffu, a0, off);
        a1 += __shfl_xor_sync(0xffffffffu, a1, off);
        a2 += __shfl_xor_sync(0xffffffffu, a2, off);
        a3 += __shfl_xor_sync(0xffffffffu, a3, off);
    }
    if (lane == 0) {
        float l0 = a0, l1 = a1, l2 = a2, l3 = a3;
        // argmax (strict >, keeps lowest index on ties like jax top_k)
        int i1 = 0; float v1 = l0;
        if (l1 > v1) { v1 = l1; i1 = 1; }
        if (l2 > v1) { v1 = l2; i1 = 2; }
        if (l3 > v1) { v1 = l3; i1 = 3; }
        int i2 = -1; float v2 = -3.4e38f;
        if (i1 != 0 && l0 > v2) { v2 = l0; i2 = 0; }
        if (i1 != 1 && l1 > v2) { v2 = l1; i2 = 1; }
        if (i1 != 2 && l2 > v2) { v2 = l2; i2 = 2; }
        if (i1 != 3 && l3 > v2) { v2 = l3; i2 = 3; }
        float e2  = __expf(v2 - v1);          // <= 1, no overflow
        float inv = 1.0f / (1.0f + e2);
        float g1 = LSCALE * inv;              // gate(top1) * LORA_SCALE
        float g2 = LSCALE * e2 * inv;         // gate(top2) * LORA_SCALE
        float g[4] = {0.f, 0.f, 0.f, 0.f};
        g[i1] = g1; g[i2] = g2;
        float4 gv = make_float4(g[0], g[1], g[2], g[3]);
        reinterpret_cast<float4*>(g_gates)[warp] = gv;
    }
}

// ---------------------------------------------------------------------------
// K2: mid GEMM  midp[split] = x @ A_flat^T
//   M tile 128 tokens, N = 64, K-chunk 32, 256 threads, 8x4 register tile.
// ---------------------------------------------------------------------------
#define MT2 128
#define KC2 32

__global__ __launch_bounds__(256)
void mid_kernel(const float* __restrict__ x, const float* __restrict__ A)
{
    __shared__ float xs[KC2][MT2 + 4];  // transposed x tile  [32][132] 16.9KB
    __shared__ float ws[KC2][ER + 4];   // transposed A tile  [32][68]   8.7KB

    const int t0     = blockIdx.x * MT2;
    const int split  = blockIdx.y;
    const int k0base = split * (D_DIM / KSPLIT);   // 512 per split

    const int tid = threadIdx.x;
    const int tx  = tid & 15;   // n-group: cols tx*4 .. +3
    const int ty  = tid >> 4;   // m-group: rows ty*8 .. +7

    float acc[8][4] = {};

    for (int kc = 0; kc < D_DIM / KSPLIT; kc += KC2) {
        const int k0 = k0base + kc;
        // stage x tile (128 rows x 32 k = 1024 float4), transposed xs[k][m]
        #pragma unroll
        for (int p = 0; p < 4; p++) {
            int idx = tid + p * 256;
            int row = idx >> 3;        // 0..127
            int c4  = idx & 7;         // float4 col
            float4 v = *reinterpret_cast<const float4*>(
                x + (size_t)(t0 + row) * D_DIM + k0 + c4 * 4);
            xs[c4 * 4 + 0][row] = v.x;
            xs[c4 * 4 + 1][row] = v.y;
            xs[c4 * 4 + 2][row] = v.z;
            xs[c4 * 4 + 3][row] = v.w;
        }
        // stage A tile (64 rows x 32 k = 512 float4), transposed ws[k][n]
        #pragma unroll
        for (int p = 0; p < 2; p++) {
            int idx = tid + p * 256;
            int row = idx >> 3;        // 0..63
            int c4  = idx & 7;
            float4 v = *reinterpret_cast<const float4*>(
                A + (size_t)row * D_DIM + k0 + c4 * 4);
            ws[c4 * 4 + 0][row] = v.x;
            ws[c4 * 4 + 1][row] = v.y;
            ws[c4 * 4 + 2][row] = v.z;
            ws[c4 * 4 + 3][row] = v.w;
        }
        __syncthreads();

        #pragma unroll
        for (int k = 0; k < KC2; k++) {
            float4 a0 = *reinterpret_cast<const float4*>(&xs[k][ty * 8]);
            float4 a1 = *reinterpret_cast<const float4*>(&xs[k][ty * 8 + 4]);
            float4 bv = *reinterpret_cast<const float4*>(&ws[k][tx * 4]);
            float a8[8] = {a0.x, a0.y, a0.z, a0.w, a1.x, a1.y, a1.z, a1.w};
            float b4[4] = {bv.x, bv.y, bv.z, bv.w};
            #pragma unroll
            for (int i = 0; i < 8; i++)
                #pragma unroll
                for (int j = 0; j < 4; j++)
                    acc[i][j] += a8[i] * b4[j];
        }
        __syncthreads();
    }

    #pragma unroll
    for (int i = 0; i < 8; i++) {
        float4 v = make_float4(acc[i][0], acc[i][1], acc[i][2], acc[i][3]);
        *reinterpret_cast<float4*>(&g_midp[split][t0 + ty * 8 + i][tx * 4]) = v;
    }
}

// ---------------------------------------------------------------------------
// K3: transpose B (E,O,R) -> Bf (ER, O)
// ---------------------------------------------------------------------------
__global__ __launch_bounds__(256)
void transposeB_kernel(const float* __restrict__ B)
{
    int idx = blockIdx.x * blockDim.x + threadIdx.x;
    if (idx >= ER * O_DIM) return;
    int er = idx >> 12;           // / 4096
    int o  = idx & (O_DIM - 1);
    int e  = er >> 4;
    int r  = er & 15;
    g_Bf[er][o] = B[((size_t)e * O_DIM + o) * R_RANK + r];
}

// ---------------------------------------------------------------------------
// K4: combine K-split partials + apply (scaled) gates
// ---------------------------------------------------------------------------
__global__ __launch_bounds__(256)
void combine_kernel(int T)
{
    int idx = blockIdx.x * blockDim.x + threadIdx.x;
    if (idx >= T * ER) return;
    int t  = idx >> 6;
    int er = idx & 63;
    int e  = er >> 4;
    float s = 0.f;
    #pragma unroll
    for (int p = 0; p < KSPLIT; p++) s += g_midp[p][t][er];
    g_gmid[t][er] = s * g_gates[t][e];
}

// ---------------------------------------------------------------------------
// K5: out GEMM  out = gmid (M x 64) @ Bf (64 x O)
//   M tile 128, N tile 128, K-chunk 32 (2 iters), 256 threads, 8x8 reg tile.
//   smem = 32*132*4 + 32*128*4 = 33.3 KB  (under 48 KB static limit)
// ---------------------------------------------------------------------------
#define MT5 128
#define NT5 128
#define KC5 32

__global__ __launch_bounds__(256)
void out_kernel(float* __restrict__ out)
{
    __shared__ float as[KC5][MT5 + 4];  // gmid^T chunk [32][132]
    __shared__ float bs[KC5][NT5];      // Bf chunk     [32][128]

    const int n0 = blockIdx.x * NT5;
    const int t0 = blockIdx.y * MT5;
    const int tid = threadIdx.x;
    const int tx = tid & 15;    // cols n0 + tx*8 .. +7
    const int ty = tid >> 4;    // rows t0 + ty*8 .. +7

    float acc[8][8] = {};

    for (int kc = 0; kc < ER; kc += KC5) {   // 2 iterations
        // stage gmid chunk (128 rows x 32 k = 1024 float4), transposed
        #pragma unroll
        for (int p = 0; p < 4; p++) {
            int idx = tid + p * 256;
            int row = idx >> 3;     // 0..127
            int c4  = idx & 7;
            float4 v = *reinterpret_cast<const float4*>(&g_gmid[t0 + row][kc + c4 * 4]);
            as[c4 * 4 + 0][row] = v.x;
            as[c4 * 4 + 1][row] = v.y;
            as[c4 * 4 + 2][row] = v.z;
            as[c4 * 4 + 3][row] = v.w;
        }
        // stage Bf chunk (32 rows x 128 n = 1024 float4), direct layout
        #pragma unroll
        for (int p = 0; p < 4; p++) {
            int idx = tid + p * 256;
            int row = idx >> 5;     // 0..31
            int c4  = idx & 31;
            float4 v = *reinterpret_cast<const float4*>(&g_Bf[kc + row][n0 + c4 * 4]);
            *reinterpret_cast<float4*>(&bs[row][c4 * 4]) = v;
        }
        __syncthreads();

        #pragma unroll
        for (int k = 0; k < KC5; k++) {
            float4 a0 = *reinterpret_cast<const float4*>(&as[k][ty * 8]);
            float4 a1 = *reinterpret_cast<const float4*>(&as[k][ty * 8 + 4]);
            float4 b0 = *reinterpret_cast<const float4*>(&bs[k][tx * 8]);
            float4 b1 = *reinterpret_cast<const float4*>(&bs[k][tx * 8 + 4]);
            float a8[8] = {a0.x, a0.y, a0.z, a0.w, a1.x, a1.y, a1.z, a1.w};
            float b8[8] = {b0.x, b0.y, b0.z, b0.w, b1.x, b1.y, b1.z, b1.w};
            #pragma unroll
            for (int i = 0; i < 8; i++)
                #pragma unroll
                for (int j = 0; j < 8; j++)
                    acc[i][j] += a8[i] * b8[j];
        }
        __syncthreads();
    }

    #pragma unroll
    for (int i = 0; i < 8; i++) {
        float* op = out + (size_t)(t0 + ty * 8 + i) * O_DIM + n0 + tx * 8;
        *reinterpret_cast<float4*>(op) =
            make_float4(acc[i][0], acc[i][1], acc[i][2], acc[i][3]);
        *reinterpret_cast<float4*>(op + 4) =
            make_float4(acc[i][4], acc[i][5], acc[i][6], acc[i][7]);
    }
}

// ---------------------------------------------------------------------------
// launch
// ---------------------------------------------------------------------------
extern "C" void kernel_launch(void* const* d_in, const int* in_sizes, int n_in,
                              void* d_out, int out_size)
{
    const float* x  = (const float*)d_in[0];   // (T, D)
    const float* rw = (const float*)d_in[1];   // (E, D)
    const float* A  = (const float*)d_in[2];   // (E, R, D) == (64, D)
    const float* B  = (const float*)d_in[3];   // (E, O, R)
    float* out = (float*)d_out;                // (T, O)

    int T = in_sizes[0] / D_DIM;               // 8192

    router_kernel<<<(T * 32 + 255) / 256, 256>>>(x, rw, T);
    mid_kernel<<<dim3(T / MT2, KSPLIT), 256>>>(x, A);
    transposeB_kernel<<<(ER * O_DIM + 255) / 256, 256>>>(B);
    combine_kernel<<<(T * ER + 255) / 256, 256>>>(T);
    out_kernel<<<dim3(O_DIM / NT5, T / MT5), 256>>>(out);
}